// round 3
// baseline (speedup 1.0000x reference)
#include <cuda_runtime.h>
#include <cstdint>
#include <cstddef>

#define BATCH 4
#define SEQ 2048
#define DMODEL 384
#define NHEADS 6
#define HD 64
#define BH (BATCH*NHEADS)      /* 24 */
#define NROWS (BH*SEQ)         /* 49152 */

// ---------------- scratch (static device allocations; no cudaMalloc allowed) ----
__device__ int8_t g_Q  [(size_t)BH*SEQ*HD];       // [b][h][n][d] int8
__device__ int8_t g_K  [(size_t)BH*SEQ*HD];       // [b][h][n][d] int8
__device__ int8_t g_Vt [(size_t)BH*HD*SEQ];       // [b][h][d][n] int8 (transposed for AV dp4a)
__device__ int8_t g_S  [(size_t)BH*SEQ*SEQ];      // logits int8, then attn uint8 in-place (100MB)
__device__ int8_t g_ctx[(size_t)BATCH*SEQ*DMODEL];// [b][n][h*hd] int8
__device__ int    g_rmax[NROWS];
__device__ int    g_rinv[NROWS];

__device__ __forceinline__ int dp4a_us(unsigned a, int b, int c) {
    int d;
    asm("dp4a.u32.s32 %0, %1, %2, %3;" : "=r"(d) : "r"(a), "r"(b), "r"(c));
    return d;
}

__device__ __forceinline__ int clamp_i8(int v) {
    return v < -128 ? -128 : (v > 127 ? 127 : v);
}

// ---------------------------------------------------------------------------
// Kernel 1: QKV projection.  Y = requantize(x @ W^T + b, 16384, 8) -> int8
// grid (8192/64, 384/64, 3), block 256 (16x16 threads, 4x4 micro-tile)
// ---------------------------------------------------------------------------
__global__ void proj_kernel(const float* __restrict__ x,
                            const float* __restrict__ wq, const float* __restrict__ bq,
                            const float* __restrict__ wk, const float* __restrict__ bk,
                            const float* __restrict__ wv, const float* __restrict__ bv)
{
    __shared__ float xs[64][17];
    __shared__ float ws[64][17];

    const int z  = blockIdx.z;
    const float* w    = (z == 0) ? wq : ((z == 1) ? wk : wv);
    const float* bias = (z == 0) ? bq : ((z == 1) ? bk : bv);

    const int m0 = blockIdx.x * 64;
    const int n0 = blockIdx.y * 64;
    const int tid = threadIdx.x;
    const int tx = tid & 15;
    const int ty = tid >> 4;

    float acc[4][4] = {};

    for (int k0 = 0; k0 < DMODEL; k0 += 16) {
        #pragma unroll
        for (int i = 0; i < 4; i++) {
            int idx = tid + i * 256;
            int r = idx >> 4, c = idx & 15;
            xs[r][c] = x[(size_t)(m0 + r) * DMODEL + k0 + c];
            ws[r][c] = w[(size_t)(n0 + r) * DMODEL + k0 + c];
        }
        __syncthreads();
        #pragma unroll
        for (int kk = 0; kk < 16; kk++) {
            float a[4], b[4];
            #pragma unroll
            for (int i = 0; i < 4; i++) a[i] = xs[ty * 4 + i][kk];
            #pragma unroll
            for (int j = 0; j < 4; j++) b[j] = ws[tx * 4 + j][kk];
            #pragma unroll
            for (int i = 0; i < 4; i++)
                #pragma unroll
                for (int j = 0; j < 4; j++)
                    acc[i][j] += a[i] * b[j];
        }
        __syncthreads();
    }

    #pragma unroll
    for (int i = 0; i < 4; i++) {
        int m = m0 + ty * 4 + i;
        int b = m >> 11;          // batch
        int n = m & 2047;         // seq pos
        #pragma unroll
        for (int j = 0; j < 4; j++) {
            int c = n0 + tx * 4 + j;
            int h = c >> 6;
            int d = c & 63;
            float v = acc[i][j] + bias[c];
            // requantize(v, 16384, 8) replicating reference rounding order:
            float r = v * 16384.0f;
            r = r * (1.0f / 256.0f);       // exact power-of-2 division
            r = floorf(r);
            r = fminf(fmaxf(r, -128.0f), 127.0f);
            int8_t q = (int8_t)(int)r;
            if (z == 2) {
                g_Vt[((size_t)(b * NHEADS + h) * HD + d) * SEQ + n] = q;
            } else if (z == 0) {
                g_Q[((size_t)(b * NHEADS + h) * SEQ + n) * HD + d] = q;
            } else {
                g_K[((size_t)(b * NHEADS + h) * SEQ + n) * HD + d] = q;
            }
        }
    }
}

// ---------------------------------------------------------------------------
// Kernel 2: logits = requantize(Q @ K^T, 5, 12) -> int8 (exact integer math)
// grid (2048/64 k-tiles, 2048/64 q-tiles, 24), block 256
// ---------------------------------------------------------------------------
__global__ void logits_kernel()
{
    __shared__ int qs[64][17];
    __shared__ int ks[64][17];

    const int bh = blockIdx.z;
    const int k0t = blockIdx.x * 64;
    const int q0t = blockIdx.y * 64;
    const int tid = threadIdx.x;
    const int tx = tid & 15;
    const int ty = tid >> 4;

    const int* Qw = (const int*)g_Q + (size_t)bh * SEQ * (HD / 4);
    const int* Kw = (const int*)g_K + (size_t)bh * SEQ * (HD / 4);

    #pragma unroll
    for (int i = 0; i < 4; i++) {
        int idx = tid + i * 256;
        int r = idx >> 4, c = idx & 15;
        qs[r][c] = Qw[(size_t)(q0t + r) * 16 + c];
        ks[r][c] = Kw[(size_t)(k0t + r) * 16 + c];
    }
    __syncthreads();

    int acc[4][4] = {};
    #pragma unroll
    for (int kk = 0; kk < 16; kk++) {
        int a[4], b[4];
        #pragma unroll
        for (int i = 0; i < 4; i++) a[i] = qs[ty * 4 + i][kk];
        #pragma unroll
        for (int j = 0; j < 4; j++) b[j] = ks[tx * 4 + j][kk];
        #pragma unroll
        for (int i = 0; i < 4; i++)
            #pragma unroll
            for (int j = 0; j < 4; j++)
                acc[i][j] = __dp4a(a[i], b[j], acc[i][j]);
    }

    int8_t* Srow = g_S + (size_t)bh * SEQ * SEQ;
    #pragma unroll
    for (int i = 0; i < 4; i++) {
        int q = q0t + ty * 4 + i;
        #pragma unroll
        for (int j = 0; j < 4; j++) {
            int k = k0t + tx * 4 + j;
            int v = (acc[i][j] * 5) >> 12;       // floor(acc*5/4096), exact
            Srow[(size_t)q * SEQ + k] = (int8_t)clamp_i8(v);
        }
    }
}

// ---------------------------------------------------------------------------
// Kernel 3: ITA softmax scan (sequential over 128 groups of 16 keys per row).
// One thread per row; pure integer, exact replica of the reference lax.scan.
// ---------------------------------------------------------------------------
__global__ void scan_kernel()
{
    int row = blockIdx.x * blockDim.x + threadIdx.x;
    if (row >= NROWS) return;

    const int4* p = (const int4*)(g_S + (size_t)row * SEQ);
    int gmax = -128;
    int ps = 0;

    for (int g = 0; g < SEQ / 16; g++) {
        int4 w = p[g];
        int words[4] = {w.x, w.y, w.z, w.w};
        // group max via SIMD byte max
        int mw = __vmaxs4(__vmaxs4(w.x, w.y), __vmaxs4(w.z, w.w));
        int cmax = -128;
        #pragma unroll
        for (int b = 0; b < 4; b++) {
            int v = (int)(int8_t)((unsigned)mw >> (8 * b));
            cmax = max(cmax, v);
        }
        if (cmax > gmax) {
            int sh = cmax - gmax;
            ps = (sh < 31) ? (ps >> sh) : 0;
            gmax = cmax;
        }
        int es = 0;
        #pragma unroll
        for (int jw = 0; jw < 4; jw++) {
            int wv = words[jw];
            #pragma unroll
            for (int b = 0; b < 4; b++) {
                int xv = (int)(int8_t)((unsigned)wv >> (8 * b));
                int df = gmax - xv;              // >= 0, <= 255
                es += (df < 9) ? (256 >> df) : 0;
            }
        }
        ps += es;
    }
    g_rmax[row] = gmax;
    g_rinv[row] = 65280 / ps;   // exact == floor(65280.0/ps), ps >= 256
}

// ---------------------------------------------------------------------------
// Kernel 4: attn write: attn[k] = inv >> (gmax - x[k]), in-place over g_S.
// One int4 (16 bytes) per thread.
// ---------------------------------------------------------------------------
__global__ void attn_kernel()
{
    size_t i = (size_t)blockIdx.x * blockDim.x + threadIdx.x;
    const size_t n4 = (size_t)BH * SEQ * (SEQ / 16);
    if (i >= n4) return;

    int row = (int)(i / (SEQ / 16));
    int4 w = ((const int4*)g_S)[i];
    int gmax = g_rmax[row];
    int inv  = g_rinv[row];

    int in[4] = {w.x, w.y, w.z, w.w};
    int out[4];
    #pragma unroll
    for (int jw = 0; jw < 4; jw++) {
        unsigned o = 0;
        #pragma unroll
        for (int b = 0; b < 4; b++) {
            int xv = (int)(int8_t)((unsigned)in[jw] >> (8 * b));
            int df = gmax - xv;
            if (df > 31) df = 31;
            unsigned a = (unsigned)(inv >> df);   // <= 255
            o |= a << (8 * b);
        }
        out[jw] = (int)o;
    }
    ((int4*)g_S)[i] = make_int4(out[0], out[1], out[2], out[3]);
}

// ---------------------------------------------------------------------------
// Kernel 5: ctx = requantize(attn @ V, 1, 8) -> int8 [b][n][h*hd]
// grid (32 q-tiles, 24 bh), block 256.  dp4a.u32.s32 over K=2048.
// ---------------------------------------------------------------------------
__global__ void av_kernel()
{
    __shared__ unsigned as_[64][17];
    __shared__ int      vs [64][17];

    const int bh = blockIdx.y;
    const int q0 = blockIdx.x * 64;
    const int tid = threadIdx.x;
    const int tx = tid & 15;
    const int ty = tid >> 4;

    const unsigned* Aw = (const unsigned*)g_S + (size_t)bh * SEQ * (SEQ / 4);
    const int*      Vw = (const int*)g_Vt + (size_t)bh * HD * (SEQ / 4);

    int acc[4][4] = {};

    for (int k0 = 0; k0 < SEQ / 4; k0 += 16) {   // chunk of 64 keys = 16 words
        #pragma unroll
        for (int i = 0; i < 4; i++) {
            int idx = tid + i * 256;
            int r = idx >> 4, c = idx & 15;
            as_[r][c] = Aw[(size_t)(q0 + r) * (SEQ / 4) + k0 + c];
            vs [r][c] = Vw[(size_t)r * (SEQ / 4) + k0 + c];
        }
        __syncthreads();
        #pragma unroll
        for (int kk = 0; kk < 16; kk++) {
            unsigned a[4]; int b[4];
            #pragma unroll
            for (int i = 0; i < 4; i++) a[i] = as_[ty * 4 + i][kk];
            #pragma unroll
            for (int j = 0; j < 4; j++) b[j] = vs[tx * 4 + j][kk];
            #pragma unroll
            for (int i = 0; i < 4; i++)
                #pragma unroll
                for (int j = 0; j < 4; j++)
                    acc[i][j] = dp4a_us(a[i], b[j], acc[i][j]);
        }
        __syncthreads();
    }

    const int b = bh / NHEADS;
    const int h = bh % NHEADS;
    #pragma unroll
    for (int i = 0; i < 4; i++) {
        int q = q0 + ty * 4 + i;
        #pragma unroll
        for (int j = 0; j < 4; j++) {
            int d = tx * 4 + j;
            int v = acc[i][j] >> 8;              // floor(acc/256), exact
            g_ctx[((size_t)b * SEQ + q) * DMODEL + h * HD + d] = (int8_t)clamp_i8(v);
        }
    }
}

// ---------------------------------------------------------------------------
// Kernel 6: out = requantize(ctx @ wo^T + bo, 256, 7) -> float32
// grid (128, 6), block 256
// ---------------------------------------------------------------------------
__global__ void out_kernel(const float* __restrict__ wo, const float* __restrict__ bo,
                           float* __restrict__ out)
{
    __shared__ float cs[64][17];
    __shared__ float ws[64][17];

    const int m0 = blockIdx.x * 64;
    const int n0 = blockIdx.y * 64;
    const int tid = threadIdx.x;
    const int tx = tid & 15;
    const int ty = tid >> 4;

    float acc[4][4] = {};

    for (int k0 = 0; k0 < DMODEL; k0 += 16) {
        #pragma unroll
        for (int i = 0; i < 4; i++) {
            int idx = tid + i * 256;
            int r = idx >> 4, c = idx & 15;
            cs[r][c] = (float)g_ctx[(size_t)(m0 + r) * DMODEL + k0 + c];
            ws[r][c] = wo[(size_t)(n0 + r) * DMODEL + k0 + c];
        }
        __syncthreads();
        #pragma unroll
        for (int kk = 0; kk < 16; kk++) {
            float a[4], b[4];
            #pragma unroll
            for (int i = 0; i < 4; i++) a[i] = cs[ty * 4 + i][kk];
            #pragma unroll
            for (int j = 0; j < 4; j++) b[j] = ws[tx * 4 + j][kk];
            #pragma unroll
            for (int i = 0; i < 4; i++)
                #pragma unroll
                for (int j = 0; j < 4; j++)
                    acc[i][j] += a[i] * b[j];
        }
        __syncthreads();
    }

    #pragma unroll
    for (int i = 0; i < 4; i++) {
        int m = m0 + ty * 4 + i;
        #pragma unroll
        for (int j = 0; j < 4; j++) {
            int c = n0 + tx * 4 + j;
            float v = acc[i][j] + bo[c];
            float r = v * 256.0f;
            r = r * (1.0f / 128.0f);             // exact
            r = floorf(r);
            r = fminf(fmaxf(r, -128.0f), 127.0f);
            out[(size_t)m * DMODEL + c] = r;
        }
    }
}

// ---------------------------------------------------------------------------
extern "C" void kernel_launch(void* const* d_in, const int* in_sizes, int n_in,
                              void* d_out, int out_size)
{
    const float* x  = (const float*)d_in[0];
    const float* wq = (const float*)d_in[1];
    const float* bq = (const float*)d_in[2];
    const float* wk = (const float*)d_in[3];
    const float* bk = (const float*)d_in[4];
    const float* wv = (const float*)d_in[5];
    const float* bv = (const float*)d_in[6];
    const float* wo = (const float*)d_in[7];
    const float* bo = (const float*)d_in[8];
    float* out = (float*)d_out;

    proj_kernel<<<dim3(128, 6, 3), 256>>>(x, wq, bq, wk, bk, wv, bv);
    logits_kernel<<<dim3(32, 32, 24), 256>>>();
    scan_kernel<<<NROWS / 256, 256>>>();
    attn_kernel<<<(unsigned)(((size_t)BH * SEQ * (SEQ / 16)) / 256), 256>>>();
    av_kernel<<<dim3(32, 24), 256>>>();
    out_kernel<<<dim3(128, 6), 256>>>(wo, bo, out);
}

// round 4
// speedup vs baseline: 1.0012x; 1.0012x over previous
#include <cuda_runtime.h>
#include <cstdint>
#include <cstddef>

#define BATCH 4
#define SEQ 2048
#define DMODEL 384
#define NHEADS 6
#define HD 64
#define BH (BATCH*NHEADS)      /* 24 */
#define NROWS (BH*SEQ)         /* 49152 */

// ---------------- scratch (static device allocations; no cudaMalloc allowed) ----
__device__ int8_t g_Q  [(size_t)BH*SEQ*HD];       // [b][h][n][d] int8
__device__ int8_t g_K  [(size_t)BH*SEQ*HD];       // [b][h][n][d] int8
__device__ int8_t g_Vt [(size_t)BH*HD*SEQ];       // [b][h][d][n] int8 (transposed for AV dp4a)
__device__ int8_t g_S  [(size_t)BH*SEQ*SEQ];      // logits int8, then attn uint8 in-place (100MB)
__device__ int8_t g_ctx[(size_t)BATCH*SEQ*DMODEL];// [b][n][h*hd] int8
__device__ int    g_rmax[NROWS];
__device__ int    g_rinv[NROWS];

__device__ __forceinline__ int dp4a_us(unsigned a, int b, int c) {
    int d;
    asm("dp4a.u32.s32 %0, %1, %2, %3;" : "=r"(d) : "r"(a), "r"(b), "r"(c));
    return d;
}

__device__ __forceinline__ int clamp_i8(int v) {
    return v < -128 ? -128 : (v > 127 ? 127 : v);
}

// ---------------------------------------------------------------------------
// Kernel 1: QKV projection.  Y = requantize(x @ W^T + b, 16384, 8) -> int8
// grid (8192/64, 384/64, 3), block 256 (16x16 threads, 4x4 micro-tile)
// ---------------------------------------------------------------------------
__global__ void proj_kernel(const float* __restrict__ x,
                            const float* __restrict__ wq, const float* __restrict__ bq,
                            const float* __restrict__ wk, const float* __restrict__ bk,
                            const float* __restrict__ wv, const float* __restrict__ bv)
{
    __shared__ float xs[64][17];
    __shared__ float ws[64][17];

    const int z  = blockIdx.z;
    const float* w    = (z == 0) ? wq : ((z == 1) ? wk : wv);
    const float* bias = (z == 0) ? bq : ((z == 1) ? bk : bv);

    const int m0 = blockIdx.x * 64;
    const int n0 = blockIdx.y * 64;
    const int tid = threadIdx.x;
    const int tx = tid & 15;
    const int ty = tid >> 4;

    float acc[4][4] = {};

    for (int k0 = 0; k0 < DMODEL; k0 += 16) {
        #pragma unroll
        for (int i = 0; i < 4; i++) {
            int idx = tid + i * 256;
            int r = idx >> 4, c = idx & 15;
            xs[r][c] = x[(size_t)(m0 + r) * DMODEL + k0 + c];
            ws[r][c] = w[(size_t)(n0 + r) * DMODEL + k0 + c];
        }
        __syncthreads();
        #pragma unroll
        for (int kk = 0; kk < 16; kk++) {
            float a[4], b[4];
            #pragma unroll
            for (int i = 0; i < 4; i++) a[i] = xs[ty * 4 + i][kk];
            #pragma unroll
            for (int j = 0; j < 4; j++) b[j] = ws[tx * 4 + j][kk];
            #pragma unroll
            for (int i = 0; i < 4; i++)
                #pragma unroll
                for (int j = 0; j < 4; j++)
                    acc[i][j] += a[i] * b[j];
        }
        __syncthreads();
    }

    #pragma unroll
    for (int i = 0; i < 4; i++) {
        int m = m0 + ty * 4 + i;
        int b = m >> 11;          // batch
        int n = m & 2047;         // seq pos
        #pragma unroll
        for (int j = 0; j < 4; j++) {
            int c = n0 + tx * 4 + j;
            int h = c >> 6;
            int d = c & 63;
            float v = acc[i][j] + bias[c];
            // requantize(v, 16384, 8) replicating reference rounding order:
            float r = v * 16384.0f;
            r = r * (1.0f / 256.0f);       // exact power-of-2 division
            r = floorf(r);
            r = fminf(fmaxf(r, -128.0f), 127.0f);
            int8_t q = (int8_t)(int)r;
            if (z == 2) {
                g_Vt[((size_t)(b * NHEADS + h) * HD + d) * SEQ + n] = q;
            } else if (z == 0) {
                g_Q[((size_t)(b * NHEADS + h) * SEQ + n) * HD + d] = q;
            } else {
                g_K[((size_t)(b * NHEADS + h) * SEQ + n) * HD + d] = q;
            }
        }
    }
}

// ---------------------------------------------------------------------------
// Kernel 2: logits = requantize(Q @ K^T, 5, 12) -> int8 (exact integer math)
// grid (2048/64 k-tiles, 2048/64 q-tiles, 24), block 256
// ---------------------------------------------------------------------------
__global__ void logits_kernel()
{
    __shared__ int qs[64][17];
    __shared__ int ks[64][17];

    const int bh = blockIdx.z;
    const int k0t = blockIdx.x * 64;
    const int q0t = blockIdx.y * 64;
    const int tid = threadIdx.x;
    const int tx = tid & 15;
    const int ty = tid >> 4;

    const int* Qw = (const int*)g_Q + (size_t)bh * SEQ * (HD / 4);
    const int* Kw = (const int*)g_K + (size_t)bh * SEQ * (HD / 4);

    #pragma unroll
    for (int i = 0; i < 4; i++) {
        int idx = tid + i * 256;
        int r = idx >> 4, c = idx & 15;
        qs[r][c] = Qw[(size_t)(q0t + r) * 16 + c];
        ks[r][c] = Kw[(size_t)(k0t + r) * 16 + c];
    }
    __syncthreads();

    int acc[4][4] = {};
    #pragma unroll
    for (int kk = 0; kk < 16; kk++) {
        int a[4], b[4];
        #pragma unroll
        for (int i = 0; i < 4; i++) a[i] = qs[ty * 4 + i][kk];
        #pragma unroll
        for (int j = 0; j < 4; j++) b[j] = ks[tx * 4 + j][kk];
        #pragma unroll
        for (int i = 0; i < 4; i++)
            #pragma unroll
            for (int j = 0; j < 4; j++)
                acc[i][j] = __dp4a(a[i], b[j], acc[i][j]);
    }

    int8_t* Srow = g_S + (size_t)bh * SEQ * SEQ;
    #pragma unroll
    for (int i = 0; i < 4; i++) {
        int q = q0t + ty * 4 + i;
        #pragma unroll
        for (int j = 0; j < 4; j++) {
            int k = k0t + tx * 4 + j;
            int v = (acc[i][j] * 5) >> 12;       // floor(acc*5/4096), exact
            Srow[(size_t)q * SEQ + k] = (int8_t)clamp_i8(v);
        }
    }
}

// ---------------------------------------------------------------------------
// Kernel 3: ITA softmax scan (sequential over 128 groups of 16 keys per row).
// One thread per row; pure integer, exact replica of the reference lax.scan.
// ---------------------------------------------------------------------------
__global__ void scan_kernel()
{
    int row = blockIdx.x * blockDim.x + threadIdx.x;
    if (row >= NROWS) return;

    const int4* p = (const int4*)(g_S + (size_t)row * SEQ);
    int gmax = -128;
    int ps = 0;

    for (int g = 0; g < SEQ / 16; g++) {
        int4 w = p[g];
        int words[4] = {w.x, w.y, w.z, w.w};
        // group max via SIMD byte max
        int mw = __vmaxs4(__vmaxs4(w.x, w.y), __vmaxs4(w.z, w.w));
        int cmax = -128;
        #pragma unroll
        for (int b = 0; b < 4; b++) {
            int v = (int)(int8_t)((unsigned)mw >> (8 * b));
            cmax = max(cmax, v);
        }
        if (cmax > gmax) {
            int sh = cmax - gmax;
            ps = (sh < 31) ? (ps >> sh) : 0;
            gmax = cmax;
        }
        int es = 0;
        #pragma unroll
        for (int jw = 0; jw < 4; jw++) {
            int wv = words[jw];
            #pragma unroll
            for (int b = 0; b < 4; b++) {
                int xv = (int)(int8_t)((unsigned)wv >> (8 * b));
                int df = gmax - xv;              // >= 0, <= 255
                es += (df < 9) ? (256 >> df) : 0;
            }
        }
        ps += es;
    }
    g_rmax[row] = gmax;
    g_rinv[row] = 65280 / ps;   // exact == floor(65280.0/ps), ps >= 256
}

// ---------------------------------------------------------------------------
// Kernel 4: attn write: attn[k] = inv >> (gmax - x[k]), in-place over g_S.
// One int4 (16 bytes) per thread.
// ---------------------------------------------------------------------------
__global__ void attn_kernel()
{
    size_t i = (size_t)blockIdx.x * blockDim.x + threadIdx.x;
    const size_t n4 = (size_t)BH * SEQ * (SEQ / 16);
    if (i >= n4) return;

    int row = (int)(i / (SEQ / 16));
    int4 w = ((const int4*)g_S)[i];
    int gmax = g_rmax[row];
    int inv  = g_rinv[row];

    int in[4] = {w.x, w.y, w.z, w.w};
    int out[4];
    #pragma unroll
    for (int jw = 0; jw < 4; jw++) {
        unsigned o = 0;
        #pragma unroll
        for (int b = 0; b < 4; b++) {
            int xv = (int)(int8_t)((unsigned)in[jw] >> (8 * b));
            int df = gmax - xv;
            if (df > 31) df = 31;
            unsigned a = (unsigned)(inv >> df);   // <= 255
            o |= a << (8 * b);
        }
        out[jw] = (int)o;
    }
    ((int4*)g_S)[i] = make_int4(out[0], out[1], out[2], out[3]);
}

// ---------------------------------------------------------------------------
// Kernel 5: ctx = requantize(attn @ V, 1, 8) -> int8 [b][n][h*hd]
// grid (32 q-tiles, 24 bh), block 256.  dp4a.u32.s32 over K=2048.
// ---------------------------------------------------------------------------
__global__ void av_kernel()
{
    __shared__ unsigned as_[64][17];
    __shared__ int      vs [64][17];

    const int bh = blockIdx.y;
    const int q0 = blockIdx.x * 64;
    const int tid = threadIdx.x;
    const int tx = tid & 15;
    const int ty = tid >> 4;

    const unsigned* Aw = (const unsigned*)g_S + (size_t)bh * SEQ * (SEQ / 4);
    const int*      Vw = (const int*)g_Vt + (size_t)bh * HD * (SEQ / 4);

    int acc[4][4] = {};

    for (int k0 = 0; k0 < SEQ / 4; k0 += 16) {   // chunk of 64 keys = 16 words
        #pragma unroll
        for (int i = 0; i < 4; i++) {
            int idx = tid + i * 256;
            int r = idx >> 4, c = idx & 15;
            as_[r][c] = Aw[(size_t)(q0 + r) * (SEQ / 4) + k0 + c];
            vs [r][c] = Vw[(size_t)r * (SEQ / 4) + k0 + c];
        }
        __syncthreads();
        #pragma unroll
        for (int kk = 0; kk < 16; kk++) {
            unsigned a[4]; int b[4];
            #pragma unroll
            for (int i = 0; i < 4; i++) a[i] = as_[ty * 4 + i][kk];
            #pragma unroll
            for (int j = 0; j < 4; j++) b[j] = vs[tx * 4 + j][kk];
            #pragma unroll
            for (int i = 0; i < 4; i++)
                #pragma unroll
                for (int j = 0; j < 4; j++)
                    acc[i][j] = dp4a_us(a[i], b[j], acc[i][j]);
        }
        __syncthreads();
    }

    const int b = bh / NHEADS;
    const int h = bh % NHEADS;
    #pragma unroll
    for (int i = 0; i < 4; i++) {
        int q = q0 + ty * 4 + i;
        #pragma unroll
        for (int j = 0; j < 4; j++) {
            int d = tx * 4 + j;
            int v = acc[i][j] >> 8;              // floor(acc/256), exact
            g_ctx[((size_t)b * SEQ + q) * DMODEL + h * HD + d] = (int8_t)clamp_i8(v);
        }
    }
}

// ---------------------------------------------------------------------------
// Kernel 6: out = requantize(ctx @ wo^T + bo, 256, 7) -> float32
// grid (128, 6), block 256
// ---------------------------------------------------------------------------
__global__ void out_kernel(const float* __restrict__ wo, const float* __restrict__ bo,
                           float* __restrict__ out)
{
    __shared__ float cs[64][17];
    __shared__ float ws[64][17];

    const int m0 = blockIdx.x * 64;
    const int n0 = blockIdx.y * 64;
    const int tid = threadIdx.x;
    const int tx = tid & 15;
    const int ty = tid >> 4;

    float acc[4][4] = {};

    for (int k0 = 0; k0 < DMODEL; k0 += 16) {
        #pragma unroll
        for (int i = 0; i < 4; i++) {
            int idx = tid + i * 256;
            int r = idx >> 4, c = idx & 15;
            cs[r][c] = (float)g_ctx[(size_t)(m0 + r) * DMODEL + k0 + c];
            ws[r][c] = wo[(size_t)(n0 + r) * DMODEL + k0 + c];
        }
        __syncthreads();
        #pragma unroll
        for (int kk = 0; kk < 16; kk++) {
            float a[4], b[4];
            #pragma unroll
            for (int i = 0; i < 4; i++) a[i] = cs[ty * 4 + i][kk];
            #pragma unroll
            for (int j = 0; j < 4; j++) b[j] = ws[tx * 4 + j][kk];
            #pragma unroll
            for (int i = 0; i < 4; i++)
                #pragma unroll
                for (int j = 0; j < 4; j++)
                    acc[i][j] += a[i] * b[j];
        }
        __syncthreads();
    }

    #pragma unroll
    for (int i = 0; i < 4; i++) {
        int m = m0 + ty * 4 + i;
        #pragma unroll
        for (int j = 0; j < 4; j++) {
            int c = n0 + tx * 4 + j;
            float v = acc[i][j] + bo[c];
            float r = v * 256.0f;
            r = r * (1.0f / 128.0f);             // exact
            r = floorf(r);
            r = fminf(fmaxf(r, -128.0f), 127.0f);
            out[(size_t)m * DMODEL + c] = r;
        }
    }
}

// ---------------------------------------------------------------------------
extern "C" void kernel_launch(void* const* d_in, const int* in_sizes, int n_in,
                              void* d_out, int out_size)
{
    const float* x  = (const float*)d_in[0];
    const float* wq = (const float*)d_in[1];
    const float* bq = (const float*)d_in[2];
    const float* wk = (const float*)d_in[3];
    const float* bk = (const float*)d_in[4];
    const float* wv = (const float*)d_in[5];
    const float* bv = (const float*)d_in[6];
    const float* wo = (const float*)d_in[7];
    const float* bo = (const float*)d_in[8];
    float* out = (float*)d_out;

    proj_kernel<<<dim3(128, 6, 3), 256>>>(x, wq, bq, wk, bk, wv, bv);
    logits_kernel<<<dim3(32, 32, 24), 256>>>();
    scan_kernel<<<NROWS / 256, 256>>>();
    attn_kernel<<<(unsigned)(((size_t)BH * SEQ * (SEQ / 16)) / 256), 256>>>();
    av_kernel<<<dim3(32, 24), 256>>>();
    out_kernel<<<dim3(128, 6), 256>>>(wo, bo, out);
}